// round 3
// baseline (speedup 1.0000x reference)
#include <cuda_runtime.h>
#include <math.h>

#define BATCH   2
#define CIN     512
#define NSEQ    2048
#define HEADS   16
#define DHEAD   64
#define HDIM    1024           // HEADS*DHEAD
#define O3      3072           // 3*HDIM
#define ATT_SCALE 8.0f

// Scratch (device globals: allocation-free scratch per harness rules)
__device__ float g_qkv[BATCH * O3 * NSEQ];     // [b][o][n], q/k normalized in place
__device__ float g_ao [BATCH * HDIM * NSEQ];   // attention output [b][c][n]

// ---------------------------------------------------------------------------
// Tiled SGEMM: Out[b][m][n] = sum_k W[m][k] * X[b][k][n] (+ bias[m])
// 64x64 tile, 256 threads (16x16), 4x4 micro-tile, K-step 16.
// ---------------------------------------------------------------------------
__global__ __launch_bounds__(256)
void sgemm_kernel(const float* __restrict__ W,
                  const float* __restrict__ X,
                  float* __restrict__ Out,
                  const float* __restrict__ bias,
                  int M, int K, int N)
{
    __shared__ float Ws[16][68];   // [k][m] (transposed), padded, 16B-aligned rows
    __shared__ float Xs[16][68];   // [k][n], padded

    const int tid = threadIdx.x;
    const int tx = tid & 15;        // n micro
    const int ty = tid >> 4;        // m micro
    const int m0 = blockIdx.y * 64;
    const int n0 = blockIdx.x * 64;
    const int b  = blockIdx.z;

    const float* Xb  = X  + (size_t)b * K * N;
    float*       Ob  = Out + (size_t)b * M * N;

    float acc[4][4] = {};

    for (int k0 = 0; k0 < K; k0 += 16) {
        // load W tile (64m x 16k) transposed into Ws[k][m]
        #pragma unroll
        for (int r = 0; r < 4; r++) {
            int e = tid + r * 256;        // 0..1023
            int m = e >> 4, k = e & 15;
            Ws[k][m] = W[(size_t)(m0 + m) * K + (k0 + k)];
        }
        // load X tile (16k x 64n)
        #pragma unroll
        for (int r = 0; r < 4; r++) {
            int e = tid + r * 256;
            int k = e >> 6, n = e & 63;
            Xs[k][n] = Xb[(size_t)(k0 + k) * N + (n0 + n)];
        }
        __syncthreads();

        #pragma unroll
        for (int k = 0; k < 16; k++) {
            float4 wv = *(const float4*)&Ws[k][ty * 4];
            float4 xv = *(const float4*)&Xs[k][tx * 4];
            acc[0][0] += wv.x * xv.x; acc[0][1] += wv.x * xv.y;
            acc[0][2] += wv.x * xv.z; acc[0][3] += wv.x * xv.w;
            acc[1][0] += wv.y * xv.x; acc[1][1] += wv.y * xv.y;
            acc[1][2] += wv.y * xv.z; acc[1][3] += wv.y * xv.w;
            acc[2][0] += wv.z * xv.x; acc[2][1] += wv.z * xv.y;
            acc[2][2] += wv.z * xv.z; acc[2][3] += wv.z * xv.w;
            acc[3][0] += wv.w * xv.x; acc[3][1] += wv.w * xv.y;
            acc[3][2] += wv.w * xv.z; acc[3][3] += wv.w * xv.w;
        }
        __syncthreads();
    }

    #pragma unroll
    for (int i = 0; i < 4; i++) {
        int m = m0 + ty * 4 + i;
        float bb = bias ? bias[m] : 0.0f;
        float4 r;
        r.x = acc[i][0] + bb; r.y = acc[i][1] + bb;
        r.z = acc[i][2] + bb; r.w = acc[i][3] + bb;
        *(float4*)&Ob[(size_t)m * N + n0 + tx * 4] = r;
    }
}

// ---------------------------------------------------------------------------
// L2 normalization of q,k over head-dim (in place in g_qkv), applying scales.
// grid: (NSEQ/256, HEADS, BATCH*2)   z = b*2 + which(0=q, 1=k)
// ---------------------------------------------------------------------------
__global__ __launch_bounds__(256)
void l2norm_kernel(float* __restrict__ qkv,
                   const float* __restrict__ qs,
                   const float* __restrict__ ks)
{
    const int n  = blockIdx.x * 256 + threadIdx.x;
    const int h  = blockIdx.y;
    const int bw = blockIdx.z;
    const int b  = bw >> 1;
    const int w  = bw & 1;
    const float* sc = w ? ks : qs;

    float* base = qkv + ((size_t)b * O3 + (size_t)w * HDIM + (size_t)h * DHEAD) * NSEQ + n;

    float ss = 0.0f;
    #pragma unroll
    for (int d = 0; d < DHEAD; d++) {
        float v = base[(size_t)d * NSEQ];
        ss += v * v;
    }
    float inv = 1.0f / fmaxf(sqrtf(ss), 1e-12f);
    #pragma unroll
    for (int d = 0; d < DHEAD; d++) {
        base[(size_t)d * NSEQ] = base[(size_t)d * NSEQ] * inv * sc[d];
    }
}

// ---------------------------------------------------------------------------
// Flash attention, fp32. One block = 64 query rows of one (b,h).
// 256 threads: tx = tid&15 (16 col/d groups of 4), ty = tid>>4 (16 row groups of 4)
// smem: Qs[64][64] (d-major, pre-scaled by ATT_SCALE), Ks[64][64] (d-major),
//       Vs[64][68] (d-major padded), Ps[64][68] (i-major padded)
// ---------------------------------------------------------------------------
#define ATT_SMEM_FLOATS (64*64 + 64*64 + 64*68 + 64*68)
#define ATT_SMEM_BYTES  (ATT_SMEM_FLOATS * 4)

__global__ __launch_bounds__(256)
void attn_kernel(const float* __restrict__ qkv, float* __restrict__ ao)
{
    extern __shared__ float sm[];
    float* Qs = sm;                   // [d][i]  stride 64
    float* Ks = Qs + 64 * 64;         // [d][j]  stride 64
    float* Vs = Ks + 64 * 64;         // [d][j]  stride 68
    float* Ps = Vs + 64 * 68;         // [i][j]  stride 68

    const int tid = threadIdx.x;
    const int tx = tid & 15;
    const int ty = tid >> 4;
    const int i0 = blockIdx.x * 64;
    const int h  = blockIdx.y;
    const int b  = blockIdx.z;

    const float* qb = qkv + ((size_t)b * O3 + (size_t)h * DHEAD) * NSEQ;
    const float* kb = qb + (size_t)HDIM * NSEQ;
    const float* vb = qb + (size_t)(2 * HDIM) * NSEQ;

    // Q tile: [d][i], pre-multiplied by attention scale
    for (int e = tid; e < 64 * 64; e += 256) {
        int d = e >> 6, i = e & 63;
        Qs[d * 64 + i] = qb[(size_t)d * NSEQ + i0 + i] * ATT_SCALE;
    }

    float m[4], l[4], O[4][4];
    #pragma unroll
    for (int i = 0; i < 4; i++) {
        m[i] = -1e30f; l[i] = 0.0f;
        #pragma unroll
        for (int d = 0; d < 4; d++) O[i][d] = 0.0f;
    }

    for (int j0 = 0; j0 < NSEQ; j0 += 64) {
        __syncthreads();   // protect Ks/Vs from prior iteration's readers
        for (int e = tid; e < 64 * 64; e += 256) {
            int d = e >> 6, j = e & 63;
            float kvv = kb[(size_t)d * NSEQ + j0 + j];
            float vvv = vb[(size_t)d * NSEQ + j0 + j];
            Ks[d * 64 + j] = kvv;
            Vs[d * 68 + j] = vvv;
        }
        __syncthreads();

        // S = (scaled Q)^T K   -> s[ii][jj], rows i0+ty*4+ii, cols j0+tx*4+jj
        float s[4][4] = {};
        #pragma unroll
        for (int d = 0; d < 64; d++) {
            float4 qv = *(const float4*)&Qs[d * 64 + ty * 4];
            float4 kv = *(const float4*)&Ks[d * 64 + tx * 4];
            s[0][0] += qv.x * kv.x; s[0][1] += qv.x * kv.y;
            s[0][2] += qv.x * kv.z; s[0][3] += qv.x * kv.w;
            s[1][0] += qv.y * kv.x; s[1][1] += qv.y * kv.y;
            s[1][2] += qv.y * kv.z; s[1][3] += qv.y * kv.w;
            s[2][0] += qv.z * kv.x; s[2][1] += qv.z * kv.y;
            s[2][2] += qv.z * kv.z; s[2][3] += qv.z * kv.w;
            s[3][0] += qv.w * kv.x; s[3][1] += qv.w * kv.y;
            s[3][2] += qv.w * kv.z; s[3][3] += qv.w * kv.w;
        }

        // online softmax per row (row group = 16 lanes sharing ty)
        #pragma unroll
        for (int ii = 0; ii < 4; ii++) {
            float tm = fmaxf(fmaxf(s[ii][0], s[ii][1]), fmaxf(s[ii][2], s[ii][3]));
            #pragma unroll
            for (int off = 1; off < 16; off <<= 1)
                tm = fmaxf(tm, __shfl_xor_sync(0xffffffffu, tm, off));

            float mn   = fmaxf(m[ii], tm);
            float corr = __expf(m[ii] - mn);
            m[ii] = mn;

            float4 p;
            p.x = __expf(s[ii][0] - mn);
            p.y = __expf(s[ii][1] - mn);
            p.z = __expf(s[ii][2] - mn);
            p.w = __expf(s[ii][3] - mn);
            float rs = p.x + p.y + p.z + p.w;
            #pragma unroll
            for (int off = 1; off < 16; off <<= 1)
                rs += __shfl_xor_sync(0xffffffffu, rs, off);

            l[ii] = l[ii] * corr + rs;
            #pragma unroll
            for (int dd = 0; dd < 4; dd++) O[ii][dd] *= corr;

            *(float4*)&Ps[(ty * 4 + ii) * 68 + tx * 4] = p;
        }
        __syncthreads();

        // O[i][d] += sum_j P[i][j] * V[d][j]   (d slice = tx*4..tx*4+3)
        #pragma unroll
        for (int j4 = 0; j4 < 64; j4 += 4) {
            float4 pr[4], vr[4];
            #pragma unroll
            for (int ii = 0; ii < 4; ii++)
                pr[ii] = *(const float4*)&Ps[(ty * 4 + ii) * 68 + j4];
            #pragma unroll
            for (int dd = 0; dd < 4; dd++)
                vr[dd] = *(const float4*)&Vs[(tx * 4 + dd) * 68 + j4];
            #pragma unroll
            for (int ii = 0; ii < 4; ii++) {
                #pragma unroll
                for (int dd = 0; dd < 4; dd++) {
                    O[ii][dd] += pr[ii].x * vr[dd].x + pr[ii].y * vr[dd].y
                               + pr[ii].z * vr[dd].z + pr[ii].w * vr[dd].w;
                }
            }
        }
    }
    __syncthreads();

    // normalize and transpose through smem (reuse Qs as [d][i]) for coalesced store
    float invl[4];
    #pragma unroll
    for (int ii = 0; ii < 4; ii++) invl[ii] = 1.0f / l[ii];
    #pragma unroll
    for (int ii = 0; ii < 4; ii++)
        #pragma unroll
        for (int dd = 0; dd < 4; dd++)
            Qs[(tx * 4 + dd) * 64 + ty * 4 + ii] = O[ii][dd] * invl[ii];
    __syncthreads();

    float* aob = ao + ((size_t)b * HDIM + (size_t)h * DHEAD) * NSEQ;
    for (int e = tid; e < 64 * 64; e += 256) {
        int d = e >> 6, i = e & 63;
        aob[(size_t)d * NSEQ + i0 + i] = Qs[d * 64 + i];
    }
}

// ---------------------------------------------------------------------------
extern "C" void kernel_launch(void* const* d_in, const int* in_sizes, int n_in,
                              void* d_out, int out_size)
{
    const float* x       = (const float*)d_in[0];
    const float* Wqkv    = (const float*)d_in[1];
    const float* q_scale = (const float*)d_in[2];
    const float* k_scale = (const float*)d_in[3];
    const float* Wout    = (const float*)d_in[4];
    const float* bout    = (const float*)d_in[5];
    float*       out     = (float*)d_out;

    float *qkv = nullptr, *ao = nullptr;
    cudaGetSymbolAddress((void**)&qkv, g_qkv);
    cudaGetSymbolAddress((void**)&ao,  g_ao);

    dim3 blk(256);

    // 1) QKV projection: [3072 x 512] @ [512 x 2048] per batch
    sgemm_kernel<<<dim3(NSEQ / 64, O3 / 64, BATCH), blk>>>(
        Wqkv, x, qkv, nullptr, O3, CIN, NSEQ);

    // 2) l2-normalize q,k in place (+ learned per-dim scales)
    l2norm_kernel<<<dim3(NSEQ / 256, HEADS, BATCH * 2), blk>>>(
        qkv, q_scale, k_scale);

    // 3) flash attention
    cudaFuncSetAttribute(attn_kernel, cudaFuncAttributeMaxDynamicSharedMemorySize,
                         ATT_SMEM_BYTES);
    attn_kernel<<<dim3(NSEQ / 64, HEADS, BATCH), blk, ATT_SMEM_BYTES>>>(qkv, ao);

    // 4) output projection + bias: [512 x 1024] @ [1024 x 2048] per batch
    sgemm_kernel<<<dim3(NSEQ / 64, CIN / 64, BATCH), blk>>>(
        Wout, ao, out, bout, CIN, HDIM, NSEQ);
}

// round 5
// speedup vs baseline: 1.1466x; 1.1466x over previous
#include <cuda_runtime.h>
#include <math.h>
#include <stdint.h>

#define BATCH   2
#define CIN     512
#define NSEQ    2048
#define HEADS   16
#define DHEAD   64
#define HDIM    1024           // HEADS*DHEAD
#define O3      3072           // 3*HDIM
#define ATT_SCALE 8.0f

// Scratch (device globals: allocation-free scratch per harness rules)
__device__ float g_qkv[BATCH * O3 * NSEQ];     // [b][o][n], q/k normalized in place
__device__ float g_ao [BATCH * HDIM * NSEQ];   // attention output [b][c][n]

// ===========================================================================
// tf32 helpers (baseline PTX, valid on plain sm_103 — no 'a' features)
// ===========================================================================
__device__ __forceinline__ float to_tf32(float x) {
    uint32_t u;
    asm("cvt.rna.tf32.f32 %0, %1;" : "=r"(u) : "f"(x));
    return __uint_as_float(u);
}

// D(16x8) += A(16x8 row) * B(8x8 col), tf32 inputs, fp32 accum
__device__ __forceinline__ void mma_tf32(float* d, const float4& a, const float2& b) {
    asm volatile(
        "mma.sync.aligned.m16n8k8.row.col.f32.tf32.tf32.f32 "
        "{%0,%1,%2,%3}, {%4,%5,%6,%7}, {%8,%9}, {%0,%1,%2,%3};"
        : "+f"(d[0]), "+f"(d[1]), "+f"(d[2]), "+f"(d[3])
        : "r"(__float_as_uint(a.x)), "r"(__float_as_uint(a.y)),
          "r"(__float_as_uint(a.z)), "r"(__float_as_uint(a.w)),
          "r"(__float_as_uint(b.x)), "r"(__float_as_uint(b.y)));
}

// ===========================================================================
// tf32 mma.sync GEMM: Out[b][m][n] = sum_k W[m][k] * X[b][k][n] (+ bias[m])
// CTA tile 128m x 128n, 8 warps as 4(m) x 2(n), warp tile 32m x 64n.
// K-chunk 32. Smem holds fragment-permuted tiles so each fragment load is
// one conflict-free LDS.128 (A) / LDS.64 (B).
//   A frag f = mt*4+kt (mt 0..7, kt 0..3): 128 floats, lane l holds
//     [A(g,t), A(g+8,t), A(g,t+4), A(g+8,t+4)]  g=l>>2, t=l&3 (tile-local)
//   B frag f = nt*4+kt (nt 0..15): 64 floats, lane l holds
//     [B(t,g), B(t+4,g)]   (k=t row, n=g col, tile-local)
// ===========================================================================
__global__ __launch_bounds__(256, 2)
void tf32_gemm_kernel(const float* __restrict__ W,   // [M][K]
                      const float* __restrict__ X,   // [b][K][N]
                      float* __restrict__ Out,       // [b][M][N]
                      const float* __restrict__ bias,
                      int M, int K, int N)
{
    __shared__ float As[4096];   // 32 A-frags * 128
    __shared__ float Bs[4096];   // 64 B-frags * 64

    const int tid  = threadIdx.x;
    const int wid  = tid >> 5;
    const int lane = tid & 31;
    const int g = lane >> 2;     // groupID
    const int t = lane & 3;      // threadID_in_group
    const int wm = wid >> 1;     // warp m index 0..3
    const int wn = wid & 1;      // warp n index 0..1

    const int n0 = blockIdx.x * 128;
    const int m0 = blockIdx.y * 128;
    const int b  = blockIdx.z;

    const float* Ab = W + (size_t)m0 * K;
    const float* Xb = X + (size_t)b * K * N + n0;

    float d[2][8][4];
    #pragma unroll
    for (int a = 0; a < 2; a++)
        #pragma unroll
        for (int j = 0; j < 8; j++)
            #pragma unroll
            for (int r = 0; r < 4; r++) d[a][j][r] = 0.0f;

    const int nch = K >> 5;
    for (int c = 0; c < nch; c++) {
        const int k0 = c << 5;

        // ---- stage A: each warp fills 4 fragments (conflict-free STS.128)
        #pragma unroll
        for (int i = 0; i < 4; i++) {
            int f  = wid * 4 + i;          // 0..31
            int mt = f >> 2, kt = f & 3;
            const float* ap = Ab + (size_t)(mt * 16 + g) * K + (k0 + kt * 8 + t);
            float4 v;
            v.x = to_tf32(ap[0]);
            v.y = to_tf32(ap[(size_t)8 * K]);
            v.z = to_tf32(ap[4]);
            v.w = to_tf32(ap[(size_t)8 * K + 4]);
            *(float4*)(As + f * 128 + lane * 4) = v;
        }
        // ---- stage B: each warp fills 8 fragments (conflict-free STS.64)
        #pragma unroll
        for (int i = 0; i < 8; i++) {
            int f  = wid * 8 + i;          // 0..63
            int nt = f >> 2, kt = f & 3;
            const float* bp = Xb + (size_t)(k0 + kt * 8 + t) * N + (nt * 8 + g);
            float2 v;
            v.x = to_tf32(bp[0]);
            v.y = to_tf32(bp[(size_t)4 * N]);
            *(float2*)(Bs + f * 64 + lane * 2) = v;
        }
        __syncthreads();

        // ---- compute: 4 k8-steps, 2x8 mma tiles per warp per step
        const float* Aw = As + (wm * 2) * 4 * 128;   // frag idx = mt*4+kt
        const float* Bw = Bs + (wn * 8) * 4 * 64;    // frag idx = nt*4+kt
        #pragma unroll
        for (int kt = 0; kt < 4; kt++) {
            float4 afr[2];
            afr[0] = *(const float4*)(Aw + (kt      ) * 128 + lane * 4);
            afr[1] = *(const float4*)(Aw + (kt + 4  ) * 128 + lane * 4);
            float2 bfr[8];
            #pragma unroll
            for (int j = 0; j < 8; j++)
                bfr[j] = *(const float2*)(Bw + (j * 4 + kt) * 64 + lane * 2);
            #pragma unroll
            for (int a = 0; a < 2; a++)
                #pragma unroll
                for (int j = 0; j < 8; j++)
                    mma_tf32(d[a][j], afr[a], bfr[j]);
        }
        __syncthreads();
    }

    // ---- epilogue: direct coalesced float2 stores (+bias)
    float* Ob = Out + (size_t)b * M * N;
    #pragma unroll
    for (int a = 0; a < 2; a++) {
        const int row = m0 + wm * 32 + a * 16 + g;
        const float b1 = bias ? bias[row]     : 0.0f;
        const float b2 = bias ? bias[row + 8] : 0.0f;
        #pragma unroll
        for (int j = 0; j < 8; j++) {
            const int col = n0 + wn * 64 + j * 8 + t * 2;
            float2 v0; v0.x = d[a][j][0] + b1; v0.y = d[a][j][1] + b1;
            float2 v1; v1.x = d[a][j][2] + b2; v1.y = d[a][j][3] + b2;
            *(float2*)(Ob + (size_t)row * N + col)       = v0;
            *(float2*)(Ob + (size_t)(row + 8) * N + col) = v1;
        }
    }
}

// ---------------------------------------------------------------------------
// L2 normalization of q,k over head-dim (in place in g_qkv), applying scales.
// ---------------------------------------------------------------------------
__global__ __launch_bounds__(256)
void l2norm_kernel(float* __restrict__ qkv,
                   const float* __restrict__ qs,
                   const float* __restrict__ ks)
{
    const int n  = blockIdx.x * 256 + threadIdx.x;
    const int h  = blockIdx.y;
    const int bw = blockIdx.z;
    const int b  = bw >> 1;
    const int w  = bw & 1;
    const float* sc = w ? ks : qs;

    float* base = qkv + ((size_t)b * O3 + (size_t)w * HDIM + (size_t)h * DHEAD) * NSEQ + n;

    float ss = 0.0f;
    #pragma unroll
    for (int d = 0; d < DHEAD; d++) {
        float v = base[(size_t)d * NSEQ];
        ss += v * v;
    }
    float inv = 1.0f / fmaxf(sqrtf(ss), 1e-12f);
    #pragma unroll
    for (int d = 0; d < DHEAD; d++) {
        base[(size_t)d * NSEQ] = base[(size_t)d * NSEQ] * inv * sc[d];
    }
}

// ---------------------------------------------------------------------------
// Flash attention, fp32 (unchanged — converts to tf32 mma next round).
// ---------------------------------------------------------------------------
#define ATT_SMEM_FLOATS (64*64 + 64*64 + 64*68 + 64*68)
#define ATT_SMEM_BYTES  (ATT_SMEM_FLOATS * 4)

__global__ __launch_bounds__(256)
void attn_kernel(const float* __restrict__ qkv, float* __restrict__ ao)
{
    extern __shared__ float sm[];
    float* Qs = sm;                   // [d][i]  stride 64
    float* Ks = Qs + 64 * 64;         // [d][j]  stride 64
    float* Vs = Ks + 64 * 64;         // [d][j]  stride 68
    float* Ps = Vs + 64 * 68;         // [i][j]  stride 68

    const int tid = threadIdx.x;
    const int tx = tid & 15;
    const int ty = tid >> 4;
    const int i0 = blockIdx.x * 64;
    const int h  = blockIdx.y;
    const int b  = blockIdx.z;

    const float* qb = qkv + ((size_t)b * O3 + (size_t)h * DHEAD) * NSEQ;
    const float* kb = qb + (size_t)HDIM * NSEQ;
    const float* vb = qb + (size_t)(2 * HDIM) * NSEQ;

    for (int e = tid; e < 64 * 64; e += 256) {
        int d = e >> 6, i = e & 63;
        Qs[d * 64 + i] = qb[(size_t)d * NSEQ + i0 + i] * ATT_SCALE;
    }

    float m[4], l[4], O[4][4];
    #pragma unroll
    for (int i = 0; i < 4; i++) {
        m[i] = -1e30f; l[i] = 0.0f;
        #pragma unroll
        for (int d = 0; d < 4; d++) O[i][d] = 0.0f;
    }

    for (int j0 = 0; j0 < NSEQ; j0 += 64) {
        __syncthreads();
        for (int e = tid; e < 64 * 64; e += 256) {
            int d = e >> 6, j = e & 63;
            Ks[d * 64 + j] = kb[(size_t)d * NSEQ + j0 + j];
            Vs[d * 68 + j] = vb[(size_t)d * NSEQ + j0 + j];
        }
        __syncthreads();

        float s[4][4] = {};
        #pragma unroll
        for (int d = 0; d < 64; d++) {
            float4 qv = *(const float4*)&Qs[d * 64 + ty * 4];
            float4 kv = *(const float4*)&Ks[d * 64 + tx * 4];
            s[0][0] += qv.x * kv.x; s[0][1] += qv.x * kv.y;
            s[0][2] += qv.x * kv.z; s[0][3] += qv.x * kv.w;
            s[1][0] += qv.y * kv.x; s[1][1] += qv.y * kv.y;
            s[1][2] += qv.y * kv.z; s[1][3] += qv.y * kv.w;
            s[2][0] += qv.z * kv.x; s[2][1] += qv.z * kv.y;
            s[2][2] += qv.z * kv.z; s[2][3] += qv.z * kv.w;
            s[3][0] += qv.w * kv.x; s[3][1] += qv.w * kv.y;
            s[3][2] += qv.w * kv.z; s[3][3] += qv.w * kv.w;
        }

        #pragma unroll
        for (int ii = 0; ii < 4; ii++) {
            float tm = fmaxf(fmaxf(s[ii][0], s[ii][1]), fmaxf(s[ii][2], s[ii][3]));
            #pragma unroll
            for (int off = 1; off < 16; off <<= 1)
                tm = fmaxf(tm, __shfl_xor_sync(0xffffffffu, tm, off));

            float mn   = fmaxf(m[ii], tm);
            float corr = __expf(m[ii] - mn);
            m[ii] = mn;

            float4 p;
            p.x = __expf(s[ii][0] - mn);
            p.y = __expf(s[ii][1] - mn);
            p.z = __expf(s[ii][2] - mn);
            p.w = __expf(s[ii][3] - mn);
            float rs = p.x + p.y + p.z + p.w;
            #pragma unroll
            for (int off = 1; off < 16; off <<= 1)
                rs += __shfl_xor_sync(0xffffffffu, rs, off);

            l[ii] = l[ii] * corr + rs;
            #pragma unroll
            for (int dd = 0; dd < 4; dd++) O[ii][dd] *= corr;

            *(float4*)&Ps[(ty * 4 + ii) * 68 + tx * 4] = p;
        }
        __syncthreads();

        #pragma unroll
        for (int j4 = 0; j4 < 64; j4 += 4) {
            float4 pr[4], vr[4];
            #pragma unroll
            for (int ii = 0; ii < 4; ii++)
                pr[ii] = *(const float4*)&Ps[(ty * 4 + ii) * 68 + j4];
            #pragma unroll
            for (int dd = 0; dd < 4; dd++)
                vr[dd] = *(const float4*)&Vs[(tx * 4 + dd) * 68 + j4];
            #pragma unroll
            for (int ii = 0; ii < 4; ii++) {
                #pragma unroll
                for (int dd = 0; dd < 4; dd++) {
                    O[ii][dd] += pr[ii].x * vr[dd].x + pr[ii].y * vr[dd].y
                               + pr[ii].z * vr[dd].z + pr[ii].w * vr[dd].w;
                }
            }
        }
    }
    __syncthreads();

    float invl[4];
    #pragma unroll
    for (int ii = 0; ii < 4; ii++) invl[ii] = 1.0f / l[ii];
    #pragma unroll
    for (int ii = 0; ii < 4; ii++)
        #pragma unroll
        for (int dd = 0; dd < 4; dd++)
            Qs[(tx * 4 + dd) * 64 + ty * 4 + ii] = O[ii][dd] * invl[ii];
    __syncthreads();

    float* aob = ao + ((size_t)b * HDIM + (size_t)h * DHEAD) * NSEQ;
    for (int e = tid; e < 64 * 64; e += 256) {
        int d = e >> 6, i = e & 63;
        aob[(size_t)d * NSEQ + i0 + i] = Qs[d * 64 + i];
    }
}

// ---------------------------------------------------------------------------
extern "C" void kernel_launch(void* const* d_in, const int* in_sizes, int n_in,
                              void* d_out, int out_size)
{
    const float* x       = (const float*)d_in[0];
    const float* Wqkv    = (const float*)d_in[1];
    const float* q_scale = (const float*)d_in[2];
    const float* k_scale = (const float*)d_in[3];
    const float* Wout    = (const float*)d_in[4];
    const float* bout    = (const float*)d_in[5];
    float*       out     = (float*)d_out;

    float *qkv = nullptr, *ao = nullptr;
    cudaGetSymbolAddress((void**)&qkv, g_qkv);
    cudaGetSymbolAddress((void**)&ao,  g_ao);

    cudaFuncSetAttribute(attn_kernel,
                         cudaFuncAttributeMaxDynamicSharedMemorySize, ATT_SMEM_BYTES);

    // 1) QKV projection (tf32 mma.sync): M=3072, K=512, N=2048
    tf32_gemm_kernel<<<dim3(NSEQ / 128, O3 / 128, BATCH), 256>>>(
        Wqkv, x, qkv, nullptr, O3, CIN, NSEQ);

    // 2) l2-normalize q,k in place (+ learned per-dim scales)
    l2norm_kernel<<<dim3(NSEQ / 256, HEADS, BATCH * 2), 256>>>(
        qkv, q_scale, k_scale);

    // 3) flash attention (fp32)
    attn_kernel<<<dim3(NSEQ / 64, HEADS, BATCH), 256, ATT_SMEM_BYTES>>>(qkv, ao);

    // 4) output projection (tf32 mma.sync) + bias: M=512, K=1024, N=2048
    tf32_gemm_kernel<<<dim3(NSEQ / 128, CIN / 128, BATCH), 256>>>(
        Wout, ao, out, bout, CIN, HDIM, NSEQ);
}

// round 6
// speedup vs baseline: 3.2225x; 2.8106x over previous
#include <cuda_runtime.h>
#include <math.h>
#include <stdint.h>

#define BATCH   2
#define CIN     512
#define NSEQ    2048
#define HEADS   16
#define DHEAD   64
#define HDIM    1024           // HEADS*DHEAD
#define O3      3072           // 3*HDIM
#define ATT_SCALE 8.0f

// Scratch (device globals: allocation-free scratch per harness rules)
__device__ float g_qkv[BATCH * O3 * NSEQ];     // [b][o][n], q/k normalized in place
__device__ float g_ao [BATCH * HDIM * NSEQ];   // attention output [b][c][n]

// ===========================================================================
// tf32 helpers (baseline PTX, valid on plain sm_103 — no 'a' features)
// ===========================================================================
__device__ __forceinline__ float to_tf32(float x) {
    uint32_t u;
    asm("cvt.rna.tf32.f32 %0, %1;" : "=r"(u) : "f"(x));
    return __uint_as_float(u);
}

// D(16x8) += A(16x8 row) * B(8x8 col), tf32 inputs, fp32 accum
// Proven fragment mapping (round 5):
//   a = [A(g,t), A(g+8,t), A(g,t+4), A(g+8,t+4)]   g=lane>>2, t=lane&3
//   b = [B(t,g), B(t+4,g)]                          (B indexed (k,n))
//   d = [D(g,2t), D(g,2t+1), D(g+8,2t), D(g+8,2t+1)]
__device__ __forceinline__ void mma_tf32(float* d, const float4& a, const float2& b) {
    asm volatile(
        "mma.sync.aligned.m16n8k8.row.col.f32.tf32.tf32.f32 "
        "{%0,%1,%2,%3}, {%4,%5,%6,%7}, {%8,%9}, {%0,%1,%2,%3};"
        : "+f"(d[0]), "+f"(d[1]), "+f"(d[2]), "+f"(d[3])
        : "r"(__float_as_uint(a.x)), "r"(__float_as_uint(a.y)),
          "r"(__float_as_uint(a.z)), "r"(__float_as_uint(a.w)),
          "r"(__float_as_uint(b.x)), "r"(__float_as_uint(b.y)));
}

// ===========================================================================
// tf32 mma.sync GEMM: Out[b][m][n] = sum_k W[m][k] * X[b][k][n] (+ bias[m])
// (unchanged from round 5 — proven)
// ===========================================================================
__global__ __launch_bounds__(256, 2)
void tf32_gemm_kernel(const float* __restrict__ W,   // [M][K]
                      const float* __restrict__ X,   // [b][K][N]
                      float* __restrict__ Out,       // [b][M][N]
                      const float* __restrict__ bias,
                      int M, int K, int N)
{
    __shared__ float As[4096];   // 32 A-frags * 128
    __shared__ float Bs[4096];   // 64 B-frags * 64

    const int tid  = threadIdx.x;
    const int wid  = tid >> 5;
    const int lane = tid & 31;
    const int g = lane >> 2;
    const int t = lane & 3;
    const int wm = wid >> 1;
    const int wn = wid & 1;

    const int n0 = blockIdx.x * 128;
    const int m0 = blockIdx.y * 128;
    const int b  = blockIdx.z;

    const float* Ab = W + (size_t)m0 * K;
    const float* Xb = X + (size_t)b * K * N + n0;

    float d[2][8][4];
    #pragma unroll
    for (int a = 0; a < 2; a++)
        #pragma unroll
        for (int j = 0; j < 8; j++)
            #pragma unroll
            for (int r = 0; r < 4; r++) d[a][j][r] = 0.0f;

    const int nch = K >> 5;
    for (int c = 0; c < nch; c++) {
        const int k0 = c << 5;

        #pragma unroll
        for (int i = 0; i < 4; i++) {
            int f  = wid * 4 + i;
            int mt = f >> 2, kt = f & 3;
            const float* ap = Ab + (size_t)(mt * 16 + g) * K + (k0 + kt * 8 + t);
            float4 v;
            v.x = to_tf32(ap[0]);
            v.y = to_tf32(ap[(size_t)8 * K]);
            v.z = to_tf32(ap[4]);
            v.w = to_tf32(ap[(size_t)8 * K + 4]);
            *(float4*)(As + f * 128 + lane * 4) = v;
        }
        #pragma unroll
        for (int i = 0; i < 8; i++) {
            int f  = wid * 8 + i;
            int nt = f >> 2, kt = f & 3;
            const float* bp = Xb + (size_t)(k0 + kt * 8 + t) * N + (nt * 8 + g);
            float2 v;
            v.x = to_tf32(bp[0]);
            v.y = to_tf32(bp[(size_t)4 * N]);
            *(float2*)(Bs + f * 64 + lane * 2) = v;
        }
        __syncthreads();

        const float* Aw = As + (wm * 2) * 4 * 128;
        const float* Bw = Bs + (wn * 8) * 4 * 64;
        #pragma unroll
        for (int kt = 0; kt < 4; kt++) {
            float4 afr[2];
            afr[0] = *(const float4*)(Aw + (kt    ) * 128 + lane * 4);
            afr[1] = *(const float4*)(Aw + (kt + 4) * 128 + lane * 4);
            float2 bfr[8];
            #pragma unroll
            for (int j = 0; j < 8; j++)
                bfr[j] = *(const float2*)(Bw + (j * 4 + kt) * 64 + lane * 2);
            #pragma unroll
            for (int a = 0; a < 2; a++)
                #pragma unroll
                for (int j = 0; j < 8; j++)
                    mma_tf32(d[a][j], afr[a], bfr[j]);
        }
        __syncthreads();
    }

    float* Ob = Out + (size_t)b * M * N;
    #pragma unroll
    for (int a = 0; a < 2; a++) {
        const int row = m0 + wm * 32 + a * 16 + g;
        const float b1 = bias ? bias[row]     : 0.0f;
        const float b2 = bias ? bias[row + 8] : 0.0f;
        #pragma unroll
        for (int j = 0; j < 8; j++) {
            const int col = n0 + wn * 64 + j * 8 + t * 2;
            float2 v0; v0.x = d[a][j][0] + b1; v0.y = d[a][j][1] + b1;
            float2 v1; v1.x = d[a][j][2] + b2; v1.y = d[a][j][3] + b2;
            *(float2*)(Ob + (size_t)row * N + col)       = v0;
            *(float2*)(Ob + (size_t)(row + 8) * N + col) = v1;
        }
    }
}

// ---------------------------------------------------------------------------
// L2 normalization of q,k over head-dim (in place in g_qkv), applying scales.
// ---------------------------------------------------------------------------
__global__ __launch_bounds__(256)
void l2norm_kernel(float* __restrict__ qkv,
                   const float* __restrict__ qs,
                   const float* __restrict__ ks)
{
    const int n  = blockIdx.x * 256 + threadIdx.x;
    const int h  = blockIdx.y;
    const int bw = blockIdx.z;
    const int b  = bw >> 1;
    const int w  = bw & 1;
    const float* sc = w ? ks : qs;

    float* base = qkv + ((size_t)b * O3 + (size_t)w * HDIM + (size_t)h * DHEAD) * NSEQ + n;

    float ss = 0.0f;
    #pragma unroll
    for (int d = 0; d < DHEAD; d++) {
        float v = base[(size_t)d * NSEQ];
        ss += v * v;
    }
    float inv = 1.0f / fmaxf(sqrtf(ss), 1e-12f);
    #pragma unroll
    for (int d = 0; d < DHEAD; d++) {
        base[(size_t)d * NSEQ] = base[(size_t)d * NSEQ] * inv * sc[d];
    }
}

// ===========================================================================
// Flash attention, tf32 mma.sync. One CTA = 128 query rows of one (b,h).
// 8 warps; warp w owns rows i0 + w*16 .. +15 end-to-end (softmax is intra-warp).
// smem: Ps buffer [128][72] (Q staging -> P tiles -> O transpose),
//       Ks [64][72] (K tile, [d][j]), Vs [64][72] (V tile, [d][j]).
// Q fragments live in registers for the whole j loop.
// ===========================================================================
#define ATT_PAD 72
#define ATT_PS_FLOATS (128 * ATT_PAD)
#define ATT_KS_FLOATS (64 * ATT_PAD)
#define ATT_SMEM_BYTES ((ATT_PS_FLOATS + 2 * ATT_KS_FLOATS) * 4)

__global__ __launch_bounds__(256, 2)
void attn_tc_kernel(const float* __restrict__ qkv, float* __restrict__ ao)
{
    extern __shared__ float sm[];
    float* Ps = sm;                         // 128*72 (Q stage / P / O^T)
    float* Ks = sm + ATT_PS_FLOATS;         // 64*72
    float* Vs = Ks + ATT_KS_FLOATS;         // 64*72

    const int tid  = threadIdx.x;
    const int wid  = tid >> 5;
    const int lane = tid & 31;
    const int g = lane >> 2;
    const int t = lane & 3;
    const int r0 = wid * 16;                // warp's query-row block (tile-local)

    const int i0 = blockIdx.x * 128;
    const int h  = blockIdx.y;
    const int b  = blockIdx.z;

    const float* qb = qkv + ((size_t)b * O3 + (size_t)h * DHEAD) * NSEQ;
    const float* kb = qb + (size_t)HDIM * NSEQ;
    const float* vb = qb + (size_t)(2 * HDIM) * NSEQ;

    // ---- stage Q [i][d], pre-scaled, tf32-rounded; then lift frags to regs
    for (int e = tid; e < 128 * 64; e += 256) {
        int d = e >> 7, i = e & 127;
        Ps[i * ATT_PAD + d] = to_tf32(qb[(size_t)d * NSEQ + i0 + i] * ATT_SCALE);
    }
    __syncthreads();

    float4 qf[8];
    #pragma unroll
    for (int kt = 0; kt < 8; kt++) {
        qf[kt].x = Ps[(r0 + g)     * ATT_PAD + kt * 8 + t];
        qf[kt].y = Ps[(r0 + g + 8) * ATT_PAD + kt * 8 + t];
        qf[kt].z = Ps[(r0 + g)     * ATT_PAD + kt * 8 + t + 4];
        qf[kt].w = Ps[(r0 + g + 8) * ATT_PAD + kt * 8 + t + 4];
    }
    // (no sync needed: warp w's Ps rows are only ever touched by warp w below)

    float mrow0 = -1e30f, mrow1 = -1e30f, lrow0 = 0.0f, lrow1 = 0.0f;
    float o[8][4];
    #pragma unroll
    for (int nt = 0; nt < 8; nt++)
        #pragma unroll
        for (int r = 0; r < 4; r++) o[nt][r] = 0.0f;

    for (int j0 = 0; j0 < NSEQ; j0 += 64) {
        __syncthreads();                     // Ks/Vs reuse barrier
        for (int e = tid; e < 64 * 64; e += 256) {
            int d = e >> 6, j = e & 63;
            Ks[d * ATT_PAD + j] = to_tf32(kb[(size_t)d * NSEQ + j0 + j]);
            Vs[d * ATT_PAD + j] = to_tf32(vb[(size_t)d * NSEQ + j0 + j]);
        }
        __syncthreads();

        // ---- S = Q K^T  (m=i, n=j, k=d)
        float s[8][4];
        #pragma unroll
        for (int nt = 0; nt < 8; nt++)
            #pragma unroll
            for (int r = 0; r < 4; r++) s[nt][r] = 0.0f;

        #pragma unroll
        for (int kt = 0; kt < 8; kt++) {
            #pragma unroll
            for (int nt = 0; nt < 8; nt++) {
                float2 bf;
                bf.x = Ks[(kt * 8 + t)     * ATT_PAD + nt * 8 + g];
                bf.y = Ks[(kt * 8 + t + 4) * ATT_PAD + nt * 8 + g];
                mma_tf32(s[nt], qf[kt], bf);
            }
        }

        // ---- online softmax (rows g and g+8; stats across the 4-lane t-group)
        float mx0 = -1e30f, mx1 = -1e30f;
        #pragma unroll
        for (int nt = 0; nt < 8; nt++) {
            mx0 = fmaxf(mx0, fmaxf(s[nt][0], s[nt][1]));
            mx1 = fmaxf(mx1, fmaxf(s[nt][2], s[nt][3]));
        }
        mx0 = fmaxf(mx0, __shfl_xor_sync(0xffffffffu, mx0, 1));
        mx0 = fmaxf(mx0, __shfl_xor_sync(0xffffffffu, mx0, 2));
        mx1 = fmaxf(mx1, __shfl_xor_sync(0xffffffffu, mx1, 1));
        mx1 = fmaxf(mx1, __shfl_xor_sync(0xffffffffu, mx1, 2));

        const float mn0 = fmaxf(mrow0, mx0);
        const float mn1 = fmaxf(mrow1, mx1);
        const float c0 = __expf(mrow0 - mn0);
        const float c1 = __expf(mrow1 - mn1);
        mrow0 = mn0; mrow1 = mn1;

        float sum0 = 0.0f, sum1 = 0.0f;
        #pragma unroll
        for (int nt = 0; nt < 8; nt++) {
            float p0 = __expf(s[nt][0] - mn0);
            float p1 = __expf(s[nt][1] - mn0);
            float p2 = __expf(s[nt][2] - mn1);
            float p3 = __expf(s[nt][3] - mn1);
            sum0 += p0 + p1;
            sum1 += p2 + p3;
            float2 v0; v0.x = to_tf32(p0); v0.y = to_tf32(p1);
            float2 v1; v1.x = to_tf32(p2); v1.y = to_tf32(p3);
            *(float2*)(Ps + (r0 + g)     * ATT_PAD + nt * 8 + 2 * t) = v0;
            *(float2*)(Ps + (r0 + g + 8) * ATT_PAD + nt * 8 + 2 * t) = v1;
        }
        sum0 += __shfl_xor_sync(0xffffffffu, sum0, 1);
        sum0 += __shfl_xor_sync(0xffffffffu, sum0, 2);
        sum1 += __shfl_xor_sync(0xffffffffu, sum1, 1);
        sum1 += __shfl_xor_sync(0xffffffffu, sum1, 2);
        lrow0 = lrow0 * c0 + sum0;
        lrow1 = lrow1 * c1 + sum1;

        #pragma unroll
        for (int nt = 0; nt < 8; nt++) {
            o[nt][0] *= c0; o[nt][1] *= c0;
            o[nt][2] *= c1; o[nt][3] *= c1;
        }
        __syncwarp();

        // ---- O += P V^T  (m=i, n=d, k=j)
        #pragma unroll
        for (int kt = 0; kt < 8; kt++) {
            float4 af;
            af.x = Ps[(r0 + g)     * ATT_PAD + kt * 8 + t];
            af.y = Ps[(r0 + g + 8) * ATT_PAD + kt * 8 + t];
            af.z = Ps[(r0 + g)     * ATT_PAD + kt * 8 + t + 4];
            af.w = Ps[(r0 + g + 8) * ATT_PAD + kt * 8 + t + 4];
            #pragma unroll
            for (int nt = 0; nt < 8; nt++) {
                float2 bf;
                bf.x = Vs[(nt * 8 + g) * ATT_PAD + kt * 8 + t];
                bf.y = Vs[(nt * 8 + g) * ATT_PAD + kt * 8 + t + 4];
                mma_tf32(o[nt], af, bf);
            }
        }
        __syncwarp();                        // P WAR before next tile's stores
    }
    __syncthreads();

    // ---- normalize + transpose to [d][i] through smem, coalesced store
    const float inv0 = 1.0f / lrow0;
    const float inv1 = 1.0f / lrow1;
    #pragma unroll
    for (int nt = 0; nt < 8; nt++) {
        Ps[(nt * 8 + 2 * t)     * 132 + r0 + g]     = o[nt][0] * inv0;
        Ps[(nt * 8 + 2 * t + 1) * 132 + r0 + g]     = o[nt][1] * inv0;
        Ps[(nt * 8 + 2 * t)     * 132 + r0 + g + 8] = o[nt][2] * inv1;
        Ps[(nt * 8 + 2 * t + 1) * 132 + r0 + g + 8] = o[nt][3] * inv1;
    }
    __syncthreads();

    float* aob = ao + ((size_t)b * HDIM + (size_t)h * DHEAD) * NSEQ;
    for (int e = tid; e < 64 * 128; e += 256) {
        int d = e >> 7, i = e & 127;
        aob[(size_t)d * NSEQ + i0 + i] = Ps[d * 132 + i];
    }
}

// ---------------------------------------------------------------------------
extern "C" void kernel_launch(void* const* d_in, const int* in_sizes, int n_in,
                              void* d_out, int out_size)
{
    const float* x       = (const float*)d_in[0];
    const float* Wqkv    = (const float*)d_in[1];
    const float* q_scale = (const float*)d_in[2];
    const float* k_scale = (const float*)d_in[3];
    const float* Wout    = (const float*)d_in[4];
    const float* bout    = (const float*)d_in[5];
    float*       out     = (float*)d_out;

    float *qkv = nullptr, *ao = nullptr;
    cudaGetSymbolAddress((void**)&qkv, g_qkv);
    cudaGetSymbolAddress((void**)&ao,  g_ao);

    cudaFuncSetAttribute(attn_tc_kernel,
                         cudaFuncAttributeMaxDynamicSharedMemorySize, ATT_SMEM_BYTES);

    // 1) QKV projection (tf32 mma.sync): M=3072, K=512, N=2048
    tf32_gemm_kernel<<<dim3(NSEQ / 128, O3 / 128, BATCH), 256>>>(
        Wqkv, x, qkv, nullptr, O3, CIN, NSEQ);

    // 2) l2-normalize q,k in place (+ learned per-dim scales)
    l2norm_kernel<<<dim3(NSEQ / 256, HEADS, BATCH * 2), 256>>>(
        qkv, q_scale, k_scale);

    // 3) flash attention (tf32 mma.sync)
    attn_tc_kernel<<<dim3(NSEQ / 128, HEADS, BATCH), 256, ATT_SMEM_BYTES>>>(qkv, ao);

    // 4) output projection (tf32 mma.sync) + bias: M=512, K=1024, N=2048
    tf32_gemm_kernel<<<dim3(NSEQ / 128, CIN / 128, BATCH), 256>>>(
        Wout, ao, out, bout, CIN, HDIM, NSEQ);
}

// round 7
// speedup vs baseline: 3.5011x; 1.0865x over previous
#include <cuda_runtime.h>
#include <math.h>
#include <stdint.h>

#define BATCH   2
#define CIN     512
#define NSEQ    2048
#define HEADS   16
#define DHEAD   64
#define HDIM    1024           // HEADS*DHEAD
#define O3      3072           // 3*HDIM
#define ATT_SCALE 8.0f

// Scratch (device globals: allocation-free scratch per harness rules)
__device__ float g_qkv[BATCH * O3 * NSEQ];     // [b][o][n], q/k normalized in place
__device__ float g_ao [BATCH * HDIM * NSEQ];   // attention output [b][c][n]

// ===========================================================================
// tf32 helpers (baseline PTX, valid on plain sm_103 — no 'a' features)
// ===========================================================================
__device__ __forceinline__ float to_tf32(float x) {
    uint32_t u;
    asm("cvt.rna.tf32.f32 %0, %1;" : "=r"(u) : "f"(x));
    return __uint_as_float(u);
}

// D(16x8) += A(16x8 row) * B(8x8 col), tf32 inputs, fp32 accum
// Proven fragment mapping (round 5/6):
//   a = [A(g,t), A(g+8,t), A(g,t+4), A(g+8,t+4)]   g=lane>>2, t=lane&3
//   b = [B(t,g), B(t+4,g)]                          (B indexed (k,n))
//   d = [D(g,2t), D(g,2t+1), D(g+8,2t), D(g+8,2t+1)]
__device__ __forceinline__ void mma_tf32(float* d, const float4& a, const float2& b) {
    asm volatile(
        "mma.sync.aligned.m16n8k8.row.col.f32.tf32.tf32.f32 "
        "{%0,%1,%2,%3}, {%4,%5,%6,%7}, {%8,%9}, {%0,%1,%2,%3};"
        : "+f"(d[0]), "+f"(d[1]), "+f"(d[2]), "+f"(d[3])
        : "r"(__float_as_uint(a.x)), "r"(__float_as_uint(a.y)),
          "r"(__float_as_uint(a.z)), "r"(__float_as_uint(a.w)),
          "r"(__float_as_uint(b.x)), "r"(__float_as_uint(b.y)));
}

// ===========================================================================
// tf32 mma.sync GEMM (unchanged from round 5 — proven)
// ===========================================================================
__global__ __launch_bounds__(256, 2)
void tf32_gemm_kernel(const float* __restrict__ W,   // [M][K]
                      const float* __restrict__ X,   // [b][K][N]
                      float* __restrict__ Out,       // [b][M][N]
                      const float* __restrict__ bias,
                      int M, int K, int N)
{
    __shared__ float As[4096];
    __shared__ float Bs[4096];

    const int tid  = threadIdx.x;
    const int wid  = tid >> 5;
    const int lane = tid & 31;
    const int g = lane >> 2;
    const int t = lane & 3;
    const int wm = wid >> 1;
    const int wn = wid & 1;

    const int n0 = blockIdx.x * 128;
    const int m0 = blockIdx.y * 128;
    const int b  = blockIdx.z;

    const float* Ab = W + (size_t)m0 * K;
    const float* Xb = X + (size_t)b * K * N + n0;

    float d[2][8][4];
    #pragma unroll
    for (int a = 0; a < 2; a++)
        #pragma unroll
        for (int j = 0; j < 8; j++)
            #pragma unroll
            for (int r = 0; r < 4; r++) d[a][j][r] = 0.0f;

    const int nch = K >> 5;
    for (int c = 0; c < nch; c++) {
        const int k0 = c << 5;

        #pragma unroll
        for (int i = 0; i < 4; i++) {
            int f  = wid * 4 + i;
            int mt = f >> 2, kt = f & 3;
            const float* ap = Ab + (size_t)(mt * 16 + g) * K + (k0 + kt * 8 + t);
            float4 v;
            v.x = to_tf32(ap[0]);
            v.y = to_tf32(ap[(size_t)8 * K]);
            v.z = to_tf32(ap[4]);
            v.w = to_tf32(ap[(size_t)8 * K + 4]);
            *(float4*)(As + f * 128 + lane * 4) = v;
        }
        #pragma unroll
        for (int i = 0; i < 8; i++) {
            int f  = wid * 8 + i;
            int nt = f >> 2, kt = f & 3;
            const float* bp = Xb + (size_t)(k0 + kt * 8 + t) * N + (nt * 8 + g);
            float2 v;
            v.x = to_tf32(bp[0]);
            v.y = to_tf32(bp[(size_t)4 * N]);
            *(float2*)(Bs + f * 64 + lane * 2) = v;
        }
        __syncthreads();

        const float* Aw = As + (wm * 2) * 4 * 128;
        const float* Bw = Bs + (wn * 8) * 4 * 64;
        #pragma unroll
        for (int kt = 0; kt < 4; kt++) {
            float4 afr[2];
            afr[0] = *(const float4*)(Aw + (kt    ) * 128 + lane * 4);
            afr[1] = *(const float4*)(Aw + (kt + 4) * 128 + lane * 4);
            float2 bfr[8];
            #pragma unroll
            for (int j = 0; j < 8; j++)
                bfr[j] = *(const float2*)(Bw + (j * 4 + kt) * 64 + lane * 2);
            #pragma unroll
            for (int a = 0; a < 2; a++)
                #pragma unroll
                for (int j = 0; j < 8; j++)
                    mma_tf32(d[a][j], afr[a], bfr[j]);
        }
        __syncthreads();
    }

    float* Ob = Out + (size_t)b * M * N;
    #pragma unroll
    for (int a = 0; a < 2; a++) {
        const int row = m0 + wm * 32 + a * 16 + g;
        const float b1 = bias ? bias[row]     : 0.0f;
        const float b2 = bias ? bias[row + 8] : 0.0f;
        #pragma unroll
        for (int j = 0; j < 8; j++) {
            const int col = n0 + wn * 64 + j * 8 + t * 2;
            float2 v0; v0.x = d[a][j][0] + b1; v0.y = d[a][j][1] + b1;
            float2 v1; v1.x = d[a][j][2] + b2; v1.y = d[a][j][3] + b2;
            *(float2*)(Ob + (size_t)row * N + col)       = v0;
            *(float2*)(Ob + (size_t)(row + 8) * N + col) = v1;
        }
    }
}

// ---------------------------------------------------------------------------
// L2 normalization of q,k over head-dim (in place in g_qkv), applying scales.
// ---------------------------------------------------------------------------
__global__ __launch_bounds__(256)
void l2norm_kernel(float* __restrict__ qkv,
                   const float* __restrict__ qs,
                   const float* __restrict__ ks)
{
    const int n  = blockIdx.x * 256 + threadIdx.x;
    const int h  = blockIdx.y;
    const int bw = blockIdx.z;
    const int b  = bw >> 1;
    const int w  = bw & 1;
    const float* sc = w ? ks : qs;

    float* base = qkv + ((size_t)b * O3 + (size_t)w * HDIM + (size_t)h * DHEAD) * NSEQ + n;

    float ss = 0.0f;
    #pragma unroll
    for (int d = 0; d < DHEAD; d++) {
        float v = base[(size_t)d * NSEQ];
        ss += v * v;
    }
    float inv = 1.0f / fmaxf(sqrtf(ss), 1e-12f);
    #pragma unroll
    for (int d = 0; d < DHEAD; d++) {
        base[(size_t)d * NSEQ] = base[(size_t)d * NSEQ] * inv * sc[d];
    }
}

// ===========================================================================
// Flash attention v2, tf32 mma.sync. One CTA = 128 query rows of one (b,h).
// 8 warps; warp w owns rows i0 + w*16 .. +15. BN=64 key tile.
//
// Smem (dynamic, 64KB):
//   Kf [4096]  64 B-frags (f = nt*8+kt) of 64 floats; LDS.64 conflict-free.
//   Vf [4096]  64 B-frags (f = dt*8+kt) of 64 floats; LDS.64 conflict-free.
//   Pf [8192]  per-warp A-frag buffers: warp w at Pf+w*1024, 8 frags * 128.
//   (epilogue reuses [0, 64*132) as the O^T transpose buffer)
//
// Software pipeline (2 barriers/iter):
//   STS K(j); sync; LDG V(j)->vreg; S-MMA+softmax+P-store;
//   STS V(j); sync; LDG K(j+64)->kreg; PV-MMA
// ===========================================================================
#define ATT_SMEM_BYTES (16384 * 4)

__global__ __launch_bounds__(256, 2)
void attn_tc_kernel(const float* __restrict__ qkv, float* __restrict__ ao)
{
    extern __shared__ float smf[];
    float* Kf = smf;             // 4096
    float* Vf = smf + 4096;      // 4096
    float* Pf = smf + 8192;      // 8192

    const int tid  = threadIdx.x;
    const int wid  = tid >> 5;
    const int lane = tid & 31;
    const int g = lane >> 2;
    const int t = lane & 3;
    const int r0 = wid * 16;

    const int i0 = blockIdx.x * 128;
    const int h  = blockIdx.y;
    const int b  = blockIdx.z;

    const float* qb = qkv + ((size_t)b * O3 + (size_t)h * DHEAD) * NSEQ;
    const float* kb = qb + (size_t)HDIM * NSEQ;
    const float* vb = qb + (size_t)(2 * HDIM) * NSEQ;

    float* Pw = Pf + wid * 1024;

    // ---- Q fragments straight from gmem into registers (live whole kernel)
    float4 qf[8];
    #pragma unroll
    for (int kt = 0; kt < 8; kt++) {
        const float* qp = qb + (size_t)(kt * 8 + t) * NSEQ + i0 + r0 + g;
        qf[kt].x = to_tf32(qp[0] * ATT_SCALE);
        qf[kt].y = to_tf32(qp[8] * ATT_SCALE);
        qf[kt].z = to_tf32(qp[(size_t)4 * NSEQ] * ATT_SCALE);
        qf[kt].w = to_tf32(qp[(size_t)4 * NSEQ + 8] * ATT_SCALE);
    }

    // ---- preload K tile 0 into regs (warp w stages frags f = w*8+kt, nt=w)
    float2 kreg[8];
    #pragma unroll
    for (int i = 0; i < 8; i++) {
        const float* kp = kb + (size_t)(i * 8 + t) * NSEQ + (wid * 8 + g);
        kreg[i].x = kp[0];
        kreg[i].y = kp[(size_t)4 * NSEQ];
    }

    float mrow0 = -1e30f, mrow1 = -1e30f, lrow0 = 0.0f, lrow1 = 0.0f;
    float o[8][4];
    #pragma unroll
    for (int nt = 0; nt < 8; nt++)
        #pragma unroll
        for (int r = 0; r < 4; r++) o[nt][r] = 0.0f;

    for (int j0 = 0; j0 < NSEQ; j0 += 64) {
        // ---- publish K frags (prior S-MMA readers cleared by prior V-sync)
        #pragma unroll
        for (int i = 0; i < 8; i++) {
            float2 v; v.x = to_tf32(kreg[i].x); v.y = to_tf32(kreg[i].y);
            *(float2*)(Kf + (wid * 8 + i) * 64 + lane * 2) = v;
        }
        __syncthreads();   // K ready; also clears prior-iter PV readers of Vf

        // ---- issue V loads (latency covered by S-MMA + softmax)
        float2 vreg[8];
        #pragma unroll
        for (int i = 0; i < 8; i++) {
            const float* vp = vb + (size_t)(wid * 8 + g) * NSEQ + j0 + i * 8 + t;
            vreg[i].x = vp[0];
            vreg[i].y = vp[4];
        }

        // ---- S = Q K^T  (B-frag = one LDS.64, conflict-free)
        float s[8][4];
        #pragma unroll
        for (int nt = 0; nt < 8; nt++)
            #pragma unroll
            for (int r = 0; r < 4; r++) s[nt][r] = 0.0f;

        #pragma unroll
        for (int kt = 0; kt < 8; kt++)
            #pragma unroll
            for (int nt = 0; nt < 8; nt++)
                mma_tf32(s[nt], qf[kt],
                         *(const float2*)(Kf + (nt * 8 + kt) * 64 + lane * 2));

        // ---- online softmax (rows g, g+8; stats across 4-lane t-group)
        float mx0 = -1e30f, mx1 = -1e30f;
        #pragma unroll
        for (int nt = 0; nt < 8; nt++) {
            mx0 = fmaxf(mx0, fmaxf(s[nt][0], s[nt][1]));
            mx1 = fmaxf(mx1, fmaxf(s[nt][2], s[nt][3]));
        }
        mx0 = fmaxf(mx0, __shfl_xor_sync(0xffffffffu, mx0, 1));
        mx0 = fmaxf(mx0, __shfl_xor_sync(0xffffffffu, mx0, 2));
        mx1 = fmaxf(mx1, __shfl_xor_sync(0xffffffffu, mx1, 1));
        mx1 = fmaxf(mx1, __shfl_xor_sync(0xffffffffu, mx1, 2));

        const float mn0 = fmaxf(mrow0, mx0);
        const float mn1 = fmaxf(mrow1, mx1);
        const float c0 = __expf(mrow0 - mn0);
        const float c1 = __expf(mrow1 - mn1);
        mrow0 = mn0; mrow1 = mn1;

        // P -> per-warp A-frag buffer:
        //   value P(row, col): addr = nt*128 + (row&7)*16 + (col&3)*4
        //                           + (col>=4 ? 2 : 0) + (row>=8 ? 1 : 0)
        //   {p0,p2} and {p1,p3} are address-adjacent -> 2 STS.64 per nt.
        float sum0 = 0.0f, sum1 = 0.0f;
        #pragma unroll
        for (int nt = 0; nt < 8; nt++) {
            float p0 = __expf(s[nt][0] - mn0);
            float p1 = __expf(s[nt][1] - mn0);
            float p2 = __expf(s[nt][2] - mn1);
            float p3 = __expf(s[nt][3] - mn1);
            sum0 += p0 + p1;
            sum1 += p2 + p3;
            const int c = 2 * t;
            const int base = nt * 128 + g * 16 + (c & 3) * 4 + ((c >= 4) ? 2 : 0);
            float2 e0; e0.x = to_tf32(p0); e0.y = to_tf32(p2);
            float2 e1; e1.x = to_tf32(p1); e1.y = to_tf32(p3);
            *(float2*)(Pw + base) = e0;
            const int c1i = c + 1;
            const int base1 = nt * 128 + g * 16 + (c1i & 3) * 4 + ((c1i >= 4) ? 2 : 0);
            *(float2*)(Pw + base1) = e1;
        }
        sum0 += __shfl_xor_sync(0xffffffffu, sum0, 1);
        sum0 += __shfl_xor_sync(0xffffffffu, sum0, 2);
        sum1 += __shfl_xor_sync(0xffffffffu, sum1, 1);
        sum1 += __shfl_xor_sync(0xffffffffu, sum1, 2);
        lrow0 = lrow0 * c0 + sum0;
        lrow1 = lrow1 * c1 + sum1;

        #pragma unroll
        for (int nt = 0; nt < 8; nt++) {
            o[nt][0] *= c0; o[nt][1] *= c0;
            o[nt][2] *= c1; o[nt][3] *= c1;
        }

        // ---- publish V frags
        #pragma unroll
        for (int i = 0; i < 8; i++) {
            float2 v; v.x = to_tf32(vreg[i].x); v.y = to_tf32(vreg[i].y);
            *(float2*)(Vf + (wid * 8 + i) * 64 + lane * 2) = v;
        }
        __syncthreads();   // V ready; also makes this warp's P stores ordered

        // ---- prefetch next K tile (latency covered by PV; s[] dead here)
        const int jn = (j0 + 64 < NSEQ) ? j0 + 64 : 0;
        #pragma unroll
        for (int i = 0; i < 8; i++) {
            const float* kp = kb + (size_t)(i * 8 + t) * NSEQ + jn + wid * 8 + g;
            kreg[i].x = kp[0];
            kreg[i].y = kp[(size_t)4 * NSEQ];
        }

        // ---- O += P V^T  (A-frag = LDS.128, B-frag = LDS.64, conflict-free)
        #pragma unroll
        for (int kt = 0; kt < 8; kt++) {
            float4 af = *(const float4*)(Pw + kt * 128 + lane * 4);
            #pragma unroll
            for (int nt = 0; nt < 8; nt++)
                mma_tf32(o[nt], af,
                         *(const float2*)(Vf + (nt * 8 + kt) * 64 + lane * 2));
        }
    }
    __syncthreads();

    // ---- normalize + transpose to [d][i] through smem, coalesced store
    const float inv0 = 1.0f / lrow0;
    const float inv1 = 1.0f / lrow1;
    float* Ts = smf;    // 64 x 132
    #pragma unroll
    for (int nt = 0; nt < 8; nt++) {
        Ts[(nt * 8 + 2 * t)     * 132 + r0 + g]     = o[nt][0] * inv0;
        Ts[(nt * 8 + 2 * t + 1) * 132 + r0 + g]     = o[nt][1] * inv0;
        Ts[(nt * 8 + 2 * t)     * 132 + r0 + g + 8] = o[nt][2] * inv1;
        Ts[(nt * 8 + 2 * t + 1) * 132 + r0 + g + 8] = o[nt][3] * inv1;
    }
    __syncthreads();

    float* aob = ao + ((size_t)b * HDIM + (size_t)h * DHEAD) * NSEQ;
    for (int e = tid; e < 64 * 128; e += 256) {
        int d = e >> 7, i = e & 127;
        aob[(size_t)d * NSEQ + i0 + i] = Ts[d * 132 + i];
    }
}

// ---------------------------------------------------------------------------
extern "C" void kernel_launch(void* const* d_in, const int* in_sizes, int n_in,
                              void* d_out, int out_size)
{
    const float* x       = (const float*)d_in[0];
    const float* Wqkv    = (const float*)d_in[1];
    const float* q_scale = (const float*)d_in[2];
    const float* k_scale = (const float*)d_in[3];
    const float* Wout    = (const float*)d_in[4];
    const float* bout    = (const float*)d_in[5];
    float*       out     = (float*)d_out;

    float *qkv = nullptr, *ao = nullptr;
    cudaGetSymbolAddress((void**)&qkv, g_qkv);
    cudaGetSymbolAddress((void**)&ao,  g_ao);

    cudaFuncSetAttribute(attn_tc_kernel,
                         cudaFuncAttributeMaxDynamicSharedMemorySize, ATT_SMEM_BYTES);

    // 1) QKV projection (tf32 mma.sync): M=3072, K=512, N=2048
    tf32_gemm_kernel<<<dim3(NSEQ / 128, O3 / 128, BATCH), 256>>>(
        Wqkv, x, qkv, nullptr, O3, CIN, NSEQ);

    // 2) l2-normalize q,k in place (+ learned per-dim scales)
    l2norm_kernel<<<dim3(NSEQ / 256, HEADS, BATCH * 2), 256>>>(
        qkv, q_scale, k_scale);

    // 3) flash attention (tf32 mma.sync, fragment-permuted smem + prefetch)
    attn_tc_kernel<<<dim3(NSEQ / 128, HEADS, BATCH), 256, ATT_SMEM_BYTES>>>(qkv, ao);

    // 4) output projection (tf32 mma.sync) + bias: M=512, K=1024, N=2048
    tf32_gemm_kernel<<<dim3(NSEQ / 128, CIN / 128, BATCH), 256>>>(
        Wout, ao, out, bout, CIN, HDIM, NSEQ);
}